// round 17
// baseline (speedup 1.0000x reference)
#include <cuda_runtime.h>
#include <cuda_bf16.h>

// CBOW negative-sampling loss, round 17: int8 tables (64B rows = 2 sectors/gather,
// per-row fp32 scale in-row), 4 samples/warp, two-launch reduce.
#define VOCAB 50000
#define DIM   50
#define BATCH 131072
#define CTX   10
#define NEG   10

#define THREADS  128
#define SPB      16                      // samples per block: 4 warps x 4 groups
#define NBLOCKS  (BATCH / SPB)           // 8192
#define NWL      (BATCH / 4)             // 32768 per-warp loss sums
#define RED_B    64
#define RED_T    512                     // 64*512 = 32768 exact

// int8 row layout (64B): bytes 0..49 = q[50], 50..55 = 0, 56..59 = fp32 scale, 60..63 = 0
#define ROW_U2   8                       // 8 x uint2 per row (8B per lane)

#define CVR_T    256                     // convert: 8 warps/block, 4 rows/warp
#define CVR_B    (2 * VOCAB / 32)        // 3125 blocks (exact: 3125*8*4 = 100000)

__device__ __align__(128) uint2 g_in8[VOCAB * ROW_U2];    // 3.2 MB
__device__ __align__(128) uint2 g_out8[VOCAB * ROW_U2];   // 3.2 MB
__device__ __align__(16)  float g_wl[NWL];                // per-warp loss sums
__device__ __align__(16)  float g_red[RED_B];
__device__ unsigned             g_cnt = 0;                // self-resetting counter

// ---- quantize fp32 [V,50] rows -> int8 rows with per-row scale ----
__global__ __launch_bounds__(CVR_T)
void cbow_convert(const float2* __restrict__ in2, const float2* __restrict__ out2)
{
    const int lane = threadIdx.x & 31;
    const int warp = threadIdx.x >> 5;
    const int gw   = blockIdx.x * 8 + warp;
    const unsigned FULL = 0xffffffffu;

    float2 a[4];
    #pragma unroll
    for (int k = 0; k < 4; k++) {              // front-batched coalesced reads (MLP 4)
        int r = gw * 4 + k;
        const float2* src = (r < VOCAB) ? (in2 + (size_t)r * 25)
                                        : (out2 + (size_t)(r - VOCAB) * 25);
        a[k] = (lane < 25) ? __ldg(&src[lane]) : make_float2(0.f, 0.f);
    }
    #pragma unroll
    for (int k = 0; k < 4; k++) {
        int r = gw * 4 + k;
        float m = fmaxf(fabsf(a[k].x), fabsf(a[k].y));
        #pragma unroll
        for (int o = 16; o > 0; o >>= 1)
            m = fmaxf(m, __shfl_xor_sync(FULL, m, o));
        float inv   = (m > 0.f) ? 127.0f / m : 0.f;
        float scale = m * (1.0f / 127.0f);
        int q0 = (int)rintf(a[k].x * inv);
        int q1 = (int)rintf(a[k].y * inv);
        unsigned short u = (unsigned short)((q0 & 0xff) | ((q1 & 0xff) << 8));
        unsigned char* base = (unsigned char*)((r < VOCAB) ? (g_in8 + r * ROW_U2)
                                                           : (g_out8 + (r - VOCAB) * ROW_U2));
        if      (lane < 25)  *(unsigned short*)(base + lane * 2) = u;        // dims 2l,2l+1
        else if (lane < 28)  *(unsigned short*)(base + 50 + (lane - 25) * 2) = 0; // pad 50..55
        else if (lane == 28) *(float*)(base + 56) = scale;                   // scale @56
        else if (lane == 29) *(unsigned*)(base + 60) = 0;                    // pad 60..63
    }
}

// signed byte b of packed word -> float (DP4A extract + I2F)
__device__ __forceinline__ float b2f(unsigned v, int b) {
    return (float)__dp4a((int)v, 1 << (b * 8), 0);
}

__global__ __launch_bounds__(THREADS, 12)
void cbow_main(const int* __restrict__ ctx,
               const int* __restrict__ pos,
               const int* __restrict__ neg)
{
    __shared__ int s_ctx[SPB * CTX];
    __shared__ int s_neg[SPB * NEG];
    __shared__ int s_pos[SPB];
    __shared__ __align__(16) float s_red[4][44 * 8];   // [warp][term][8 lanes]

    const int tid  = threadIdx.x;
    const int lane = tid & 31;
    const int warp = tid >> 5;
    const int grp  = lane >> 3;          // 4 samples per warp
    const int li   = lane & 7;           // 8 lanes per sample, uint2 = 8B each
    const int B0   = blockIdx.x * SPB;
    const unsigned FULL = 0xffffffffu;

    for (int i = tid; i < SPB * CTX; i += THREADS) s_ctx[i] = __ldg(&ctx[B0 * CTX + i]);
    for (int i = tid; i < SPB * NEG; i += THREADS) s_neg[i] = __ldg(&neg[B0 * NEG + i]);
    if (tid < SPB) s_pos[tid] = __ldg(&pos[B0 + tid]);
    __syncthreads();

    const int s = warp * 4 + grp;        // sample within block
    float* const red = &s_red[warp][grp * 88 + li];    // term stride 8 floats
    const bool isScaleLane = (li == 7);  // lane 7 holds bytes 56..63 (scale + pad)

    // ---- context mean: 2 groups of 5 LDG.64 (2 sectors/row), decode + scaled accum ----
    float cv[8] = {0.f, 0.f, 0.f, 0.f, 0.f, 0.f, 0.f, 0.f};
    #pragma unroll
    for (int g = 0; g < 2; g++) {
        uint2 t[5];
        #pragma unroll
        for (int c = 0; c < 5; c++) {
            int r = s_ctx[s * CTX + g * 5 + c];
            t[c] = __ldg(&g_in8[r * ROW_U2 + li]);
        }
        #pragma unroll
        for (int c = 0; c < 5; c++) {
            float sr = __shfl_sync(FULL, __uint_as_float(t[c].x), lane | 7);
            unsigned vx = isScaleLane ? 0u : t[c].x;
            unsigned vy = isScaleLane ? 0u : t[c].y;
            #pragma unroll
            for (int b = 0; b < 4; b++) cv[b]     = fmaf(sr, b2f(vx, b), cv[b]);
            #pragma unroll
            for (int b = 0; b < 4; b++) cv[4 + b] = fmaf(sr, b2f(vy, b), cv[4 + b]);
        }
    }
    #pragma unroll
    for (int d = 0; d < 8; d++) cv[d] *= (1.0f / CTX);

    // ---- 11 dots in groups of 4/4/3; scaled partials straight to transpose smem ----
    {
        uint2 t[4];
        t[0] = __ldg(&g_out8[s_pos[s] * ROW_U2 + li]);
        #pragma unroll
        for (int k = 0; k < 3; k++)
            t[k + 1] = __ldg(&g_out8[s_neg[s * NEG + k] * ROW_U2 + li]);
        #pragma unroll
        for (int j = 0; j < 4; j++) {
            float sr = __shfl_sync(FULL, __uint_as_float(t[j].x), lane | 7);
            unsigned vx = isScaleLane ? 0u : t[j].x;
            unsigned vy = isScaleLane ? 0u : t[j].y;
            float acc = 0.f;
            #pragma unroll
            for (int b = 0; b < 4; b++) acc = fmaf(b2f(vx, b), cv[b], acc);
            #pragma unroll
            for (int b = 0; b < 4; b++) acc = fmaf(b2f(vy, b), cv[4 + b], acc);
            red[j * 8] = acc * sr;
        }
    }
    {
        uint2 t[4];
        #pragma unroll
        for (int k = 0; k < 4; k++)
            t[k] = __ldg(&g_out8[s_neg[s * NEG + 3 + k] * ROW_U2 + li]);
        #pragma unroll
        for (int j = 0; j < 4; j++) {
            float sr = __shfl_sync(FULL, __uint_as_float(t[j].x), lane | 7);
            unsigned vx = isScaleLane ? 0u : t[j].x;
            unsigned vy = isScaleLane ? 0u : t[j].y;
            float acc = 0.f;
            #pragma unroll
            for (int b = 0; b < 4; b++) acc = fmaf(b2f(vx, b), cv[b], acc);
            #pragma unroll
            for (int b = 0; b < 4; b++) acc = fmaf(b2f(vy, b), cv[4 + b], acc);
            red[(4 + j) * 8] = acc * sr;
        }
    }
    {
        uint2 t[3];
        #pragma unroll
        for (int k = 0; k < 3; k++)
            t[k] = __ldg(&g_out8[s_neg[s * NEG + 7 + k] * ROW_U2 + li]);
        #pragma unroll
        for (int j = 0; j < 3; j++) {
            float sr = __shfl_sync(FULL, __uint_as_float(t[j].x), lane | 7);
            unsigned vx = isScaleLane ? 0u : t[j].x;
            unsigned vy = isScaleLane ? 0u : t[j].y;
            float acc = 0.f;
            #pragma unroll
            for (int b = 0; b < 4; b++) acc = fmaf(b2f(vx, b), cv[b], acc);
            #pragma unroll
            for (int b = 0; b < 4; b++) acc = fmaf(b2f(vy, b), cv[4 + b], acc);
            red[(8 + j) * 8] = acc * sr;
        }
    }
    __syncwarp();

    // ---- 44 terms: lane handles term=lane (+ term=lane+32 for lanes 0..11) ----
    float total;
    {
        int t0 = lane;                       // terms 0..31
        int j0 = t0 % 11;                    // j==0 -> positive score
        const float* r0 = &s_red[warp][t0 * 8];
        float4 A  = *(const float4*)(r0);
        float4 Bv = *(const float4*)(r0 + 4);
        float sc = ((A.x + A.y) + (A.z + A.w)) + ((Bv.x + Bv.y) + (Bv.z + Bv.w));
        float arg = (j0 == 0) ? sc : -sc;
        total = __logf(1.0f / (1.0f + __expf(-arg)) + 1e-10f);
    }
    {
        int t1 = lane + 32;                  // terms 32..43 on lanes 0..11
        bool v = (t1 < 44);
        int t1c = v ? t1 : 0;
        int j1 = t1c % 11;
        const float* r1 = &s_red[warp][t1c * 8];
        float4 A  = *(const float4*)(r1);
        float4 Bv = *(const float4*)(r1 + 4);
        float sc = ((A.x + A.y) + (A.z + A.w)) + ((Bv.x + Bv.y) + (Bv.z + Bv.w));
        float arg = (j1 == 0) ? sc : -sc;
        float term = __logf(1.0f / (1.0f + __expf(-arg)) + 1e-10f);
        total += v ? term : 0.f;
    }
    #pragma unroll
    for (int o = 16; o > 0; o >>= 1)
        total += __shfl_xor_sync(FULL, total, o);

    if (lane == 0) g_wl[blockIdx.x * 4 + warp] = total;  // 4-sample warp sum
}

__global__ __launch_bounds__(RED_T)
void cbow_reduce(float* __restrict__ out)
{
    __shared__ float sbuf[RED_T / 32];
    __shared__ bool  isLast;
    const int tid  = threadIdx.x;
    const int lane = tid & 31;
    const int warp = tid >> 5;
    const unsigned FULL = 0xffffffffu;

    float t = g_wl[blockIdx.x * RED_T + tid];
    #pragma unroll
    for (int o = 16; o > 0; o >>= 1)
        t += __shfl_xor_sync(FULL, t, o);
    if (lane == 0) sbuf[warp] = t;
    __syncthreads();
    if (tid < 32) {
        float v = (tid < RED_T / 32) ? sbuf[tid] : 0.f;
        #pragma unroll
        for (int o = 16; o > 0; o >>= 1)
            v += __shfl_xor_sync(FULL, v, o);
        if (tid == 0) {
            g_red[blockIdx.x] = v;
            __threadfence();
            unsigned old = atomicAdd(&g_cnt, 1u);
            isLast = (old == RED_B - 1);
        }
    }
    __syncthreads();

    if (isLast && tid < 32) {                 // deterministic fixed-order final sum
        float v = __ldcg(&g_red[tid]) + __ldcg(&g_red[tid + 32]);
        #pragma unroll
        for (int o = 16; o > 0; o >>= 1)
            v += __shfl_xor_sync(FULL, v, o);
        if (tid == 0) {
            out[0] = -v / (float)BATCH;
            g_cnt = 0;                        // reset for next graph replay
        }
    }
}

extern "C" void kernel_launch(void* const* d_in, const int* in_sizes, int n_in,
                              void* d_out, int out_size)
{
    const int*   ctx  = (const int*)d_in[0];   // [B, CTX]
    const int*   pos  = (const int*)d_in[1];   // [B]
    const int*   neg  = (const int*)d_in[2];   // [B, NEG]
    const float* inW  = (const float*)d_in[3]; // [VOCAB, DIM]
    const float* outW = (const float*)d_in[4]; // [VOCAB, DIM]
    float* out = (float*)d_out;

    cbow_convert<<<CVR_B, CVR_T>>>((const float2*)inW, (const float2*)outW);
    cbow_main<<<NBLOCKS, THREADS>>>(ctx, pos, neg);
    cbow_reduce<<<RED_B, RED_T>>>(out);
}